// round 7
// baseline (speedup 1.0000x reference)
#include <cuda_runtime.h>
#include <cstdint>

// ---------------------------------------------------------------------------
// RipsECC. B=4096 points in [0,1]^3, 64 bins, bin(d) = ceil(31.5*d) in [0,55].
// All C(4096,2)=8,386,560 pairs are edges. out = cumsum(+4096 at bin0 - hist).
//
// OCCUPANCY round: 296 blocks x 512 threads -> 2 CTAs/SM, 2048 thr/SM (100%).
// Per CTA: pts 64KB + u8 histogram 32KB (4 regions x 64 bins x 32 lanes x 4
// warp-banks per word) = 96KB -> two CTAs fit in 228KB.
// Units: per 32-row i-block b, 1 diagonal tile + chunks of 64 j's
// (NUNITS=4224 over 296x16=4736 warp slots). Lane owns i = 32b+lane.
// ---------------------------------------------------------------------------

#define NPTS      4096
#define NSTEPS    64
#define NTHREADS  512
#define NBLOCKS   296
#define NUNITS    4224
#define NREGIONS  4
#define HIST_WORDS (NREGIONS * NSTEPS * 32)        // 8192 words = 32 KB
#define SMEM_BYTES (NPTS * 16 + HIST_WORDS * 4)    // 64KB + 32KB = 98304 B

__device__ int      g_part[NBLOCKS][NSTEPS];
__device__ unsigned g_ticket = 0;

// bin = ceil(31.5*d) = ceil(sqrt(m)); m = 992.25*d2 via norm expansion.
__device__ __forceinline__ int bin_of(float A, float B, float C, float K,
                                      float4 p) {
    float m = fmaf(A, p.x, fmaf(B, p.y, fmaf(C, p.z, K + p.w)));
    float d;
    asm("sqrt.approx.f32 %0, %1;" : "=f"(d) : "f"(m));   // MUFU.SQRT
    return __float2int_ru(d);                            // t in [0, 55]
}

extern __shared__ float4 smem4[];

__global__ void __launch_bounds__(NTHREADS, 2)
rips_ecc_kernel(const float* __restrict__ x, float* __restrict__ out) {
    float4*   pts  = smem4;                       // [4096] (x,y,z, 992.25|p|^2)
    unsigned* hist = (unsigned*)(smem4 + NPTS);   // [4][64][32] u32 words

    const int tid = threadIdx.x;

    // Coalesced staging: thread t computes points 8t..8t+7 from 6 LDG.128.
    {
        const float4* xv = (const float4*)x;      // 12288 floats = 3072 float4
        #pragma unroll
        for (int h = 0; h < 2; h++) {
            float4 v0 = xv[6 * tid + 3 * h + 0];
            float4 v1 = xv[6 * tid + 3 * h + 1];
            float4 v2 = xv[6 * tid + 3 * h + 2];
            int base = 8 * tid + 4 * h;
            pts[base + 0] = make_float4(v0.x, v0.y, v0.z,
                992.25f * fmaf(v0.x, v0.x, fmaf(v0.y, v0.y, v0.z * v0.z)));
            pts[base + 1] = make_float4(v0.w, v1.x, v1.y,
                992.25f * fmaf(v0.w, v0.w, fmaf(v1.x, v1.x, v1.y * v1.y)));
            pts[base + 2] = make_float4(v1.z, v1.w, v2.x,
                992.25f * fmaf(v1.z, v1.z, fmaf(v1.w, v1.w, v2.x * v2.x)));
            pts[base + 3] = make_float4(v2.y, v2.z, v2.w,
                992.25f * fmaf(v2.y, v2.y, fmaf(v2.z, v2.z, v2.w * v2.w)));
        }
    }
    uint4* h4 = (uint4*)hist;
    #pragma unroll
    for (int i = 0; i < HIST_WORDS / 4 / NTHREADS; i++)
        h4[i * NTHREADS + tid] = make_uint4(0u, 0u, 0u, 0u);
    __syncthreads();

    const int warp = tid >> 5;   // 0..15
    const int lane = tid & 31;
    // u8 bank: region = warp>>2 (8192 B each); byte = lane*4 + (warp&3).
    unsigned char* myh = (unsigned char*)hist + (warp >> 2) * 8192 +
                         lane * 4 + (warp & 3);

    const int u = warp * NBLOCKS + blockIdx.x;    // [0, 4736)
    if (u < NUNITS) {
        // prefix(b) = b + 4096 - ((128-b)^2 >> 2); invert with sqrt guess.
        float fv = -2.0f + 2.0f * sqrtf((float)(4225 - u));
        int b = 128 - (int)fv;
        b = max(0, min(127, b));
        while (b > 0 && (b + 4096 - (((128 - b) * (128 - b)) >> 2)) > u) --b;
        while (b < 127 &&
               ((b + 1) + 4096 - (((127 - b) * (127 - b)) >> 2)) <= u) ++b;
        const int rem   = u - (b + 4096 - (((128 - b) * (128 - b)) >> 2));
        const int ibase = b << 5;

        float4 pi = pts[ibase + lane];
        const float A = -1984.5f * pi.x;   // -2 * 992.25
        const float B = -1984.5f * pi.y;
        const float C = -1984.5f * pi.z;
        const float K = pi.w;

        if (rem == 0) {
            // Diagonal 32x32 tile: j = ibase+jj, count only jj > lane.
            #pragma unroll 4
            for (int jj = 1; jj < 32; jj++) {
                float4 p = pts[ibase + jj];
                int t = bin_of(A, B, C, K, p);
                if (jj > lane)
                    myh[t << 7] += (unsigned char)1;
            }
        } else {
            int j0 = ibase + 32 + ((rem - 1) << 6);
            if (j0 + 64 <= NPTS) {
                #pragma unroll 4
                for (int jj = 0; jj < 32; jj++) {
                    float4 p0 = pts[j0 + jj];
                    float4 p1 = pts[j0 + 32 + jj];
                    int t0 = bin_of(A, B, C, K, p0);
                    int t1 = bin_of(A, B, C, K, p1);
                    myh[t0 << 7] += (unsigned char)1;  // two RMWs, same byte
                    myh[t1 << 7] += (unsigned char)1;  // slot -> in-order, ok
                }
            } else {
                #pragma unroll 4
                for (int jj = 0; jj < 32; jj++) {
                    float4 p0 = pts[j0 + jj];
                    int t0 = bin_of(A, B, C, K, p0);
                    myh[t0 << 7] += (unsigned char)1;
                }
            }
        }
    }
    __syncthreads();

    // Block reduction: warp w reduces bins [4w, 4w+4); dp4a sums the 4
    // warp-banks per word across the 4 regions.
    #pragma unroll
    for (int bb = 0; bb < 4; bb++) {
        int bin = warp * 4 + bb;
        int s = 0;
        #pragma unroll
        for (int r = 0; r < NREGIONS; r++)
            s = __dp4a((int)hist[r * 2048 + (bin << 5) + lane], 0x01010101, s);
        #pragma unroll
        for (int o = 16; o > 0; o >>= 1)
            s += __shfl_down_sync(0xffffffffu, s, o);
        if (lane == 0)
            g_part[blockIdx.x][bin] = s;
    }
    __threadfence();
    __syncthreads();

    __shared__ int s_last;
    if (tid == 0)
        s_last = (atomicAdd(&g_ticket, 1u) == NBLOCKS - 1);
    __syncthreads();
    if (!s_last) return;
    __threadfence();

    // --- last block: reduce 296x64 partials, cumsum, write, reset ---
    __shared__ int red[NSTEPS * 8];
    {
        int bin = tid & 63;
        int grp = tid >> 6;               // 0..7
        int s = 0;
        for (int b2 = grp; b2 < NBLOCKS; b2 += 8)
            s += g_part[b2][bin];
        red[bin * 8 + grp] = s;
    }
    __syncthreads();
    __shared__ int ecc[NSTEPS];
    if (tid < NSTEPS) {
        int tot = 0;
        #pragma unroll
        for (int g = 0; g < 8; g++) tot += red[tid * 8 + g];
        ecc[tid] = (tid == 0 ? NPTS : 0) - tot;
    }
    __syncthreads();
    if (tid < 32) {
        int e0 = ecc[tid];
        int e1 = ecc[tid + 32];
        #pragma unroll
        for (int d = 1; d < 32; d <<= 1) {
            int t = __shfl_up_sync(0xffffffffu, e0, d);
            if (tid >= d) e0 += t;
        }
        int tot = __shfl_sync(0xffffffffu, e0, 31);
        #pragma unroll
        for (int d = 1; d < 32; d <<= 1) {
            int t = __shfl_up_sync(0xffffffffu, e1, d);
            if (tid >= d) e1 += t;
        }
        e1 += tot;
        out[tid]      = (float)e0;
        out[tid + 32] = (float)e1;
    }
    if (tid == 0) g_ticket = 0;   // self-reset for graph replay
}

extern "C" void kernel_launch(void* const* d_in, const int* in_sizes, int n_in,
                              void* d_out, int out_size) {
    (void)in_sizes; (void)n_in; (void)out_size;
    const float* x = (const float*)d_in[0];
    float* out = (float*)d_out;

    cudaFuncSetAttribute(rips_ecc_kernel,
                         cudaFuncAttributeMaxDynamicSharedMemorySize, SMEM_BYTES);

    rips_ecc_kernel<<<NBLOCKS, NTHREADS, SMEM_BYTES>>>(x, out);
}